// round 7
// baseline (speedup 1.0000x reference)
#include <cuda_runtime.h>
#include <math.h>
#include <stdint.h>

#define T_     256
#define B_     128
#define F_     1024
#define U_     512
#define G_     2048   // 4*U
#define CODES_ 1024
#define NBLK   128

// Scratch (module-scope device allocations, permitted)
__device__ float    g_xz[(size_t)T_ * G_ * B_];   // [t][c][b]  c = gate*512+u
__device__ uint32_t g_hH[(size_t)T_ * U_ * B_];   // [t][u][b] tf32-hi plane
__device__ uint32_t g_hL[(size_t)T_ * U_ * B_];   // [t][u][b] tf32-lo plane
__device__ uint32_t g_h0[U_ * B_];                // zeros (hi & lo of h0)
__device__ unsigned g_bar;

// ---------------------------------------------------------------------------
__device__ __forceinline__ uint32_t f2t(float x) {
    uint32_t r; asm("cvt.rna.tf32.f32 %0, %1;" : "=r"(r) : "f"(x)); return r;
}
__device__ __forceinline__ void split4(float4 v, uint4& hi, uint4& lo) {
    hi.x = f2t(v.x); hi.y = f2t(v.y); hi.z = f2t(v.z); hi.w = f2t(v.w);
    lo.x = f2t(v.x - __uint_as_float(hi.x));
    lo.y = f2t(v.y - __uint_as_float(hi.y));
    lo.z = f2t(v.z - __uint_as_float(hi.z));
    lo.w = f2t(v.w - __uint_as_float(hi.w));
}
__device__ __forceinline__ void mma_tf32(float* d,
                                         const uint32_t* a, const uint32_t* b) {
    asm volatile("mma.sync.aligned.m16n8k8.row.col.f32.tf32.tf32.f32 "
        "{%0,%1,%2,%3}, {%4,%5,%6,%7}, {%8,%9}, {%0,%1,%2,%3};"
        : "+f"(d[0]), "+f"(d[1]), "+f"(d[2]), "+f"(d[3])
        : "r"(a[0]), "r"(a[1]), "r"(a[2]), "r"(a[3]), "r"(b[0]), "r"(b[1]));
}

// ---------------------------------------------------------------------------
__global__ void init_kernel() {
    int i = blockIdx.x * blockDim.x + threadIdx.x;
    if (i < U_ * B_) g_h0[i] = 0u;
    if (i == 0) g_bar = 0u;
}

// ---------------------------------------------------------------------------
// GEMM 1 (TC 3xTF32, double-buffered): xz = x @ W_in + b -> g_xz[t][col][b]
// ---------------------------------------------------------------------------
#define AS_STRIDE 36
#define BS_STRIDE 136
#define XZ_STAGE  (2 * 128 * AS_STRIDE + 2 * 32 * BS_STRIDE)
#define DN_STAGE  (4 * 32 * BS_STRIDE)

__global__ __launch_bounds__(512)
void gemm_xz_tc(const float* __restrict__ A,
                const float* __restrict__ Bm,
                const float* __restrict__ bias)
{
    extern __shared__ uint32_t smx[];

    const int tid  = threadIdx.x;
    const int lane = tid & 31, w = tid >> 5;
    const int gid  = lane >> 2, tig = lane & 3;
    const int wm   = (w >> 2) * 32, wn = (w & 3) * 32;
    const int t    = blockIdx.y;
    const int row0 = t * 128;
    const int col0 = blockIdx.x * 128;

    const int arow0 = tid >> 3,        ak4 = (tid & 7) << 2;
    const int arow1 = (tid + 512) >> 3;
    const int bkk0 = tid >> 5,         bn4 = (tid & 31) << 2;
    const int bkk1 = (tid + 512) >> 5;

    float C[2][4][4];
#pragma unroll
    for (int im = 0; im < 2; im++)
#pragma unroll
        for (int in = 0; in < 4; in++)
#pragma unroll
            for (int r = 0; r < 4; r++) C[im][in][r] = 0.f;

    float4 pa0, pa1, pb0, pb1;
    pa0 = *reinterpret_cast<const float4*>(&A[(size_t)(row0 + arow0) * F_ + ak4]);
    pa1 = *reinterpret_cast<const float4*>(&A[(size_t)(row0 + arow1) * F_ + ak4]);
    pb0 = *reinterpret_cast<const float4*>(&Bm[(size_t)bkk0 * G_ + col0 + bn4]);
    pb1 = *reinterpret_cast<const float4*>(&Bm[(size_t)bkk1 * G_ + col0 + bn4]);
    {
        uint32_t* AsH = smx;
        uint32_t* AsL = AsH + 128 * AS_STRIDE;
        uint32_t* BsH = AsL + 128 * AS_STRIDE;
        uint32_t* BsL = BsH + 32 * BS_STRIDE;
        uint4 hi, lo;
        split4(pa0, hi, lo);
        *reinterpret_cast<uint4*>(&AsH[arow0 * AS_STRIDE + ak4]) = hi;
        *reinterpret_cast<uint4*>(&AsL[arow0 * AS_STRIDE + ak4]) = lo;
        split4(pa1, hi, lo);
        *reinterpret_cast<uint4*>(&AsH[arow1 * AS_STRIDE + ak4]) = hi;
        *reinterpret_cast<uint4*>(&AsL[arow1 * AS_STRIDE + ak4]) = lo;
        split4(pb0, hi, lo);
        *reinterpret_cast<uint4*>(&BsH[bkk0 * BS_STRIDE + bn4]) = hi;
        *reinterpret_cast<uint4*>(&BsL[bkk0 * BS_STRIDE + bn4]) = lo;
        split4(pb1, hi, lo);
        *reinterpret_cast<uint4*>(&BsH[bkk1 * BS_STRIDE + bn4]) = hi;
        *reinterpret_cast<uint4*>(&BsL[bkk1 * BS_STRIDE + bn4]) = lo;
    }
    __syncthreads();

    for (int k0 = 0; k0 < F_; k0 += 32) {
        const int s = (k0 >> 5) & 1;
        uint32_t* AsH = smx + s * XZ_STAGE;
        uint32_t* AsL = AsH + 128 * AS_STRIDE;
        uint32_t* BsH = AsL + 128 * AS_STRIDE;
        uint32_t* BsL = BsH + 32 * BS_STRIDE;
        const bool more = (k0 + 32 < F_);

        if (more) {
            pa0 = *reinterpret_cast<const float4*>(
                &A[(size_t)(row0 + arow0) * F_ + k0 + 32 + ak4]);
            pa1 = *reinterpret_cast<const float4*>(
                &A[(size_t)(row0 + arow1) * F_ + k0 + 32 + ak4]);
            pb0 = *reinterpret_cast<const float4*>(
                &Bm[(size_t)(k0 + 32 + bkk0) * G_ + col0 + bn4]);
            pb1 = *reinterpret_cast<const float4*>(
                &Bm[(size_t)(k0 + 32 + bkk1) * G_ + col0 + bn4]);
        }

#pragma unroll
        for (int k8 = 0; k8 < 4; k8++) {
            uint32_t aH[2][4], aL[2][4], bH[4][2], bL[4][2];
#pragma unroll
            for (int im = 0; im < 2; im++) {
                int m = wm + im * 16;
                int p0 = (m + gid) * AS_STRIDE + k8 * 8 + tig;
                int p1 = (m + gid + 8) * AS_STRIDE + k8 * 8 + tig;
                aH[im][0] = AsH[p0];     aH[im][1] = AsH[p1];
                aH[im][2] = AsH[p0 + 4]; aH[im][3] = AsH[p1 + 4];
                aL[im][0] = AsL[p0];     aL[im][1] = AsL[p1];
                aL[im][2] = AsL[p0 + 4]; aL[im][3] = AsL[p1 + 4];
            }
#pragma unroll
            for (int in = 0; in < 4; in++) {
                int n = wn + in * 8 + gid;
                int kb = k8 * 8 + tig;
                bH[in][0] = BsH[kb * BS_STRIDE + n];
                bH[in][1] = BsH[(kb + 4) * BS_STRIDE + n];
                bL[in][0] = BsL[kb * BS_STRIDE + n];
                bL[in][1] = BsL[(kb + 4) * BS_STRIDE + n];
            }
#pragma unroll
            for (int im = 0; im < 2; im++)
#pragma unroll
                for (int in = 0; in < 4; in++) {
                    mma_tf32(C[im][in], aH[im], bH[in]);
                    mma_tf32(C[im][in], aL[im], bH[in]);
                    mma_tf32(C[im][in], aH[im], bL[in]);
                }
        }

        if (more) {
            uint32_t* nAsH = smx + (s ^ 1) * XZ_STAGE;
            uint32_t* nAsL = nAsH + 128 * AS_STRIDE;
            uint32_t* nBsH = nAsL + 128 * AS_STRIDE;
            uint32_t* nBsL = nBsH + 32 * BS_STRIDE;
            uint4 hi, lo;
            split4(pa0, hi, lo);
            *reinterpret_cast<uint4*>(&nAsH[arow0 * AS_STRIDE + ak4]) = hi;
            *reinterpret_cast<uint4*>(&nAsL[arow0 * AS_STRIDE + ak4]) = lo;
            split4(pa1, hi, lo);
            *reinterpret_cast<uint4*>(&nAsH[arow1 * AS_STRIDE + ak4]) = hi;
            *reinterpret_cast<uint4*>(&nAsL[arow1 * AS_STRIDE + ak4]) = lo;
            split4(pb0, hi, lo);
            *reinterpret_cast<uint4*>(&nBsH[bkk0 * BS_STRIDE + bn4]) = hi;
            *reinterpret_cast<uint4*>(&nBsL[bkk0 * BS_STRIDE + bn4]) = lo;
            split4(pb1, hi, lo);
            *reinterpret_cast<uint4*>(&nBsH[bkk1 * BS_STRIDE + bn4]) = hi;
            *reinterpret_cast<uint4*>(&nBsL[bkk1 * BS_STRIDE + bn4]) = lo;
            __syncthreads();
        }
    }

#pragma unroll
    for (int im = 0; im < 2; im++) {
        int b = wm + im * 16 + gid;
#pragma unroll
        for (int in = 0; in < 4; in++) {
            int n = col0 + wn + in * 8 + 2 * tig;
            float bz0 = bias[n], bz1 = bias[n + 1];
            size_t p = ((size_t)t * G_ + n) * B_;
            g_xz[p + b]           = C[im][in][0] + bz0;
            g_xz[p + B_ + b]      = C[im][in][1] + bz1;
            g_xz[p + b + 8]       = C[im][in][2] + bz0;
            g_xz[p + B_ + b + 8]  = C[im][in][3] + bz1;
        }
    }
}

// ---------------------------------------------------------------------------
// Persistent LSTM on tensor cores.
// 64 unit-blocks x 2 batch-blocks; per step: z[64b x 32c] = h[64b x 512] @ Wslice.
// W resident in SMEM as tf32 hi/lo, [n=32][k=512] stride 516 (conflict-free).
// h chunks (K=64) double-buffered, [k=64][m=64] stride 72 (conflict-free).
// ---------------------------------------------------------------------------
#define WKST 516
#define HST  72
#define CST  68
#define HBUF (2 * 64 * HST)     // u32 per h buffer (hi+lo planes)

__global__ __launch_bounds__(256)
void lstm_tc_kernel(const float* __restrict__ W_rec)
{
    extern __shared__ uint32_t sm[];
    uint32_t* WsH = sm;                       // 32*516
    uint32_t* WsL = WsH + 32 * WKST;
    uint32_t* Hs  = WsL + 32 * WKST;          // 2 bufs x [HsH(64*72) | HsL(64*72)]
    float* stash  = reinterpret_cast<float*>(Hs + 2 * HBUF);  // [n=32][m] stride 68
    float* cs     = stash + 32 * CST;         // [ul=8][b=64]

    const int tid  = threadIdx.x;
    const int lane = tid & 31, wrp = tid >> 5;
    const int gid  = lane >> 2, tig = lane & 3;
    const int wm   = (wrp & 3) * 16;          // m-tile (batch)
    const int wn   = (wrp >> 2) * 16;         // two n8-tiles at wn, wn+8
    const int ub   = blockIdx.x >> 1;         // 0..63 -> units [ub*8, ub*8+8)
    const int bb   = blockIdx.x & 1;
    const int bg0  = bb * 64;

    // Load + split W slice once: WsH/WsL[n][k], n = gate*8 + ulocal
    for (int idx = tid; idx < 32 * 512; idx += 256) {
        int c = idx & 31, k = idx >> 5;
        float wv = W_rec[(size_t)k * G_ + (c >> 3) * U_ + ub * 8 + (c & 7)];
        uint32_t hi = f2t(wv);
        WsH[c * WKST + k] = hi;
        WsL[c * WKST + k] = f2t(wv - __uint_as_float(hi));
    }
    for (int i = tid; i < 8 * 64; i += 256) cs[i] = 0.f;
    __syncthreads();

    // staging coords: 4 uint4 per plane per thread (chunk = 64k x 64m)
    const int skk[4] = { tid >> 4, (tid + 256) >> 4, (tid + 512) >> 4, (tid + 768) >> 4 };
    const int sm4 = (tid & 15) << 2;

    const int eul = tid >> 5;                 // epilogue unit 0..7
    const int eb  = (tid & 31) * 2;           // epilogue batch pair

    for (int t = 0; t < T_; t++) {
        const uint32_t* hpH = (t == 0) ? g_h0 : (g_hH + (size_t)(t - 1) * U_ * B_);
        const uint32_t* hpL = (t == 0) ? g_h0 : (g_hL + (size_t)(t - 1) * U_ * B_);
        const float* xz_t = g_xz + (size_t)t * G_ * B_;

        // prefetch epilogue xz (hidden under MAC phase)
        float2 xzv[4];
#pragma unroll
        for (int g = 0; g < 4; g++)
            xzv[g] = *reinterpret_cast<const float2*>(
                &xz_t[(size_t)(g * U_ + ub * 8 + eul) * B_ + bg0 + eb]);

        float C[2][4];
#pragma unroll
        for (int in = 0; in < 2; in++)
#pragma unroll
            for (int r = 0; r < 4; r++) C[in][r] = 0.f;

        // stage chunk 0
        uint4 pfh[4], pfl[4];
#pragma unroll
        for (int i = 0; i < 4; i++) {
            pfh[i] = *reinterpret_cast<const uint4*>(&hpH[(size_t)skk[i] * B_ + bg0 + sm4]);
            pfl[i] = *reinterpret_cast<const uint4*>(&hpL[(size_t)skk[i] * B_ + bg0 + sm4]);
        }
        {
            uint32_t* bH = Hs;
            uint32_t* bL = Hs + 64 * HST;
#pragma unroll
            for (int i = 0; i < 4; i++) {
                *reinterpret_cast<uint4*>(&bH[skk[i] * HST + sm4]) = pfh[i];
                *reinterpret_cast<uint4*>(&bL[skk[i] * HST + sm4]) = pfl[i];
            }
        }
        __syncthreads();

        for (int kc = 0; kc < 8; kc++) {
            uint32_t* bH = Hs + (kc & 1) * HBUF;
            uint32_t* bL = bH + 64 * HST;
            const bool more = (kc < 7);

            if (more) {
                const uint32_t* nH = hpH + (size_t)(kc + 1) * 64 * B_;
                const uint32_t* nL = hpL + (size_t)(kc + 1) * 64 * B_;
#pragma unroll
                for (int i = 0; i < 4; i++) {
                    pfh[i] = *reinterpret_cast<const uint4*>(&nH[(size_t)skk[i] * B_ + bg0 + sm4]);
                    pfl[i] = *reinterpret_cast<const uint4*>(&nL[(size_t)skk[i] * B_ + bg0 + sm4]);
                }
            }

            const int kwb = kc * 64;
#pragma unroll
            for (int k8 = 0; k8 < 8; k8++) {
                const int kb = k8 * 8 + tig;
                uint32_t aH[4], aL[4];
                {
                    int p0 = kb * HST + wm + gid;
                    aH[0] = bH[p0];           aH[1] = bH[p0 + 8];
                    aH[2] = bH[p0 + 4 * HST]; aH[3] = bH[p0 + 4 * HST + 8];
                    aL[0] = bL[p0];           aL[1] = bL[p0 + 8];
                    aL[2] = bL[p0 + 4 * HST]; aL[3] = bL[p0 + 4 * HST + 8];
                }
#pragma unroll
                for (int in = 0; in < 2; in++) {
                    int n = wn + in * 8 + gid;
                    uint32_t bHf[2], bLf[2];
                    bHf[0] = WsH[n * WKST + kwb + kb];
                    bHf[1] = WsH[n * WKST + kwb + kb + 4];
                    bLf[0] = WsL[n * WKST + kwb + kb];
                    bLf[1] = WsL[n * WKST + kwb + kb + 4];
                    mma_tf32(C[in], aH, bHf);
                    mma_tf32(C[in], aL, bHf);
                    mma_tf32(C[in], aH, bLf);
                }
            }

            if (more) {
                uint32_t* nbH = Hs + ((kc + 1) & 1) * HBUF;
                uint32_t* nbL = nbH + 64 * HST;
#pragma unroll
                for (int i = 0; i < 4; i++) {
                    *reinterpret_cast<uint4*>(&nbH[skk[i] * HST + sm4]) = pfh[i];
                    *reinterpret_cast<uint4*>(&nbL[skk[i] * HST + sm4]) = pfl[i];
                }
                __syncthreads();
            }
        }

        // accumulators -> stash [n][m]
        __syncthreads();
#pragma unroll
        for (int in = 0; in < 2; in++) {
            int n = wn + in * 8 + 2 * tig;
            int m = wm + gid;
            stash[n * CST + m]           = C[in][0];
            stash[(n + 1) * CST + m]     = C[in][1];
            stash[n * CST + m + 8]       = C[in][2];
            stash[(n + 1) * CST + m + 8] = C[in][3];
        }
        __syncthreads();

        // gate epilogue: 2 batch elems per thread
        float2 z[4];
#pragma unroll
        for (int g = 0; g < 4; g++) {
            z[g].x = stash[(g * 8 + eul) * CST + eb]     + xzv[g].x;
            z[g].y = stash[(g * 8 + eul) * CST + eb + 1] + xzv[g].y;
        }
        float2 cold = *reinterpret_cast<float2*>(&cs[eul * 64 + eb]);
        float2 cnew, hnew;
        {
            float ig = 1.f / (1.f + __expf(-z[0].x));
            float fg = 1.f / (1.f + __expf(-z[1].x));
            float gg = 1.f - 2.f / (1.f + __expf(2.f * z[2].x));
            float og = 1.f / (1.f + __expf(-z[3].x));
            cnew.x = fg * cold.x + ig * gg;
            hnew.x = og * (1.f - 2.f / (1.f + __expf(2.f * cnew.x)));
        }
        {
            float ig = 1.f / (1.f + __expf(-z[0].y));
            float fg = 1.f / (1.f + __expf(-z[1].y));
            float gg = 1.f - 2.f / (1.f + __expf(2.f * z[2].y));
            float og = 1.f / (1.f + __expf(-z[3].y));
            cnew.y = fg * cold.y + ig * gg;
            hnew.y = og * (1.f - 2.f / (1.f + __expf(2.f * cnew.y)));
        }
        *reinterpret_cast<float2*>(&cs[eul * 64 + eb]) = cnew;

        // write h as pre-split tf32 hi/lo planes
        uint2 hh, hl;
        hh.x = f2t(hnew.x); hl.x = f2t(hnew.x - __uint_as_float(hh.x));
        hh.y = f2t(hnew.y); hl.y = f2t(hnew.y - __uint_as_float(hh.y));
        size_t hq = (size_t)(ub * 8 + eul) * B_ + bg0 + eb;
        *reinterpret_cast<uint2*>(&g_hH[(size_t)t * U_ * B_ + hq]) = hh;
        *reinterpret_cast<uint2*>(&g_hL[(size_t)t * U_ * B_ + hq]) = hl;

        // software grid barrier
        __threadfence();
        __syncthreads();
        if (tid == 0) {
            atomicAdd(&g_bar, 1u);
            unsigned tgt = (unsigned)(NBLK * (t + 1));
            while (*((volatile unsigned*)&g_bar) < tgt) { }
            __threadfence();
        }
        __syncthreads();
    }
}

// ---------------------------------------------------------------------------
// GEMM 3 (TC 3xTF32, double-buffered): out = relu(mask*(h@W_dense)+b_dense)
// A read directly from pre-split g_hH/g_hL planes ([t][u][b] = [k][m])
// ---------------------------------------------------------------------------
__global__ __launch_bounds__(512)
void gemm_dense_tc(const float* __restrict__ Bm,
                   const float* __restrict__ bias,
                   const float* __restrict__ mask,
                   float* __restrict__ Cout)
{
    extern __shared__ uint32_t smx[];

    const int tid  = threadIdx.x;
    const int lane = tid & 31, w = tid >> 5;
    const int gid  = lane >> 2, tig = lane & 3;
    const int wm   = (w >> 2) * 32, wn = (w & 3) * 32;
    const int t    = blockIdx.y;
    const int col0 = blockIdx.x * 128;
    const uint32_t* AhH = g_hH + (size_t)t * U_ * B_;
    const uint32_t* AhL = g_hL + (size_t)t * U_ * B_;

    const int kk0 = tid >> 5, x4 = (tid & 31) << 2;
    const int kk1 = (tid + 512) >> 5;

    float C[2][4][4];
#pragma unroll
    for (int im = 0; im < 2; im++)
#pragma unroll
        for (int in = 0; in < 4; in++)
#pragma unroll
            for (int r = 0; r < 4; r++) C[im][in][r] = 0.f;

    uint4 pah0, pah1, pal0, pal1;
    float4 pb0, pb1;
    pah0 = *reinterpret_cast<const uint4*>(&AhH[(size_t)kk0 * B_ + x4]);
    pal0 = *reinterpret_cast<const uint4*>(&AhL[(size_t)kk0 * B_ + x4]);
    pah1 = *reinterpret_cast<const uint4*>(&AhH[(size_t)kk1 * B_ + x4]);
    pal1 = *reinterpret_cast<const uint4*>(&AhL[(size_t)kk1 * B_ + x4]);
    pb0 = *reinterpret_cast<const float4*>(&Bm[(size_t)kk0 * CODES_ + col0 + x4]);
    pb1 = *reinterpret_cast<const float4*>(&Bm[(size_t)kk1 * CODES_ + col0 + x4]);
    {
        uint32_t* AsH = smx;
        uint32_t* AsL = AsH + 32 * BS_STRIDE;
        uint32_t* BsH = AsL + 32 * BS_STRIDE;
        uint32_t* BsL = BsH + 32 * BS_STRIDE;
        *reinterpret_cast<uint4*>(&AsH[kk0 * BS_STRIDE + x4]) = pah0;
        *reinterpret_cast<uint4*>(&AsL[kk0 * BS_STRIDE + x4]) = pal0;
        *reinterpret_cast<uint4*>(&AsH[kk1 * BS_STRIDE + x4]) = pah1;
        *reinterpret_cast<uint4*>(&AsL[kk1 * BS_STRIDE + x4]) = pal1;
        uint4 hi, lo;
        split4(pb0, hi, lo);
        *reinterpret_cast<uint4*>(&BsH[kk0 * BS_STRIDE + x4]) = hi;
        *reinterpret_cast<uint4*>(&BsL[kk0 * BS_STRIDE + x4]) = lo;
        split4(pb1, hi, lo);
        *reinterpret_cast<uint4*>(&BsH[kk1 * BS_STRIDE + x4]) = hi;
        *reinterpret_cast<uint4*>(&BsL[kk1 * BS_STRIDE + x4]) = lo;
    }
    __syncthreads();

    for (int k0 = 0; k0 < U_; k0 += 32) {
        const int s = (k0 >> 5) & 1;
        uint32_t* AsH = smx + s * DN_STAGE;
        uint32_t* AsL = AsH + 32 * BS_STRIDE;
        uint32_t* BsH = AsL + 32 * BS_STRIDE;
        uint32_t* BsL = BsH + 32 * BS_STRIDE;
        const bool more = (k0 + 32 < U_);

        if (more) {
            pah0 = *reinterpret_cast<const uint4*>(&AhH[(size_t)(k0 + 32 + kk0) * B_ + x4]);
            pal0 = *reinterpret_cast<const uint4*>(&AhL[(size_t)(k0 + 32 + kk0) * B_ + x4]);
            pah1 = *reinterpret_cast<const uint4*>(&AhH[(size_t)(k0 + 32 + kk1) * B_ + x4]);
            pal1 = *reinterpret_cast<const uint4*>(&AhL[(size_t)(k0 + 32 + kk1) * B_ + x4]);
            pb0 = *reinterpret_cast<const float4*>(
                &Bm[(size_t)(k0 + 32 + kk0) * CODES_ + col0 + x4]);
            pb1 = *reinterpret_cast<const float4*>(
                &Bm[(size_t)(k0 + 32 + kk1) * CODES_ + col0 + x4]);
        }

#pragma unroll
        for (int k8 = 0; k8 < 4; k8++) {
            uint32_t aH[2][4], aL[2][4], bH[4][2], bL[4][2];
#pragma unroll
            for (int im = 0; im < 2; im++) {
                int m = wm + im * 16 + gid;
                int kb = k8 * 8 + tig;
                int p0 = kb * BS_STRIDE + m;
                aH[im][0] = AsH[p0];      aH[im][1] = AsH[p0 + 8];
                aH[im][2] = AsH[p0 + 4 * BS_STRIDE];
                aH[im][3] = AsH[p0 + 4 * BS_STRIDE + 8];
                aL[im][0] = AsL[p0];      aL[im][1] = AsL[p0 + 8];
                aL[im][2] = AsL[p0 + 4 * BS_STRIDE];
                aL[im][3] = AsL[p0 + 4 * BS_STRIDE + 8];
            }
#pragma unroll
            for (int in = 0; in < 4; in++) {
                int n = wn + in * 8 + gid;
                int kb = k8 * 8 + tig;
                bH[in][0] = BsH[kb * BS_STRIDE + n];
                bH[in][1] = BsH[(kb + 4) * BS_STRIDE + n];
                bL[in][0] = BsL[kb * BS_STRIDE + n];
                bL[in][1] = BsL[(kb + 4) * BS_STRIDE + n];
            }
#pragma unroll
            for (int im = 0; im < 2; im++)
#pragma unroll
                for (int in = 0; in < 4; in++) {
                    mma_tf32(C[im][in], aH[im], bH[in]);
                    mma_tf32(C[im][in], aL[im], bH[in]);
                    mma_tf32(C[im][in], aH[im], bL[in]);
                }
        }

        if (more) {
            uint32_t* nAsH = smx + (s ^ 1) * DN_STAGE;
            uint32_t* nAsL = nAsH + 32 * BS_STRIDE;
            uint32_t* nBsH = nAsL + 32 * BS_STRIDE;
            uint32_t* nBsL = nBsH + 32 * BS_STRIDE;
            *reinterpret_cast<uint4*>(&nAsH[kk0 * BS_STRIDE + x4]) = pah0;
            *reinterpret_cast<uint4*>(&nAsL[kk0 * BS_STRIDE + x4]) = pal0;
            *reinterpret_cast<uint4*>(&nAsH[kk1 * BS_STRIDE + x4]) = pah1;
            *reinterpret_cast<uint4*>(&nAsL[kk1 * BS_STRIDE + x4]) = pal1;
            uint4 hi, lo;
            split4(pb0, hi, lo);
            *reinterpret_cast<uint4*>(&nBsH[kk0 * BS_STRIDE + x4]) = hi;
            *reinterpret_cast<uint4*>(&nBsL[kk0 * BS_STRIDE + x4]) = lo;
            split4(pb1, hi, lo);
            *reinterpret_cast<uint4*>(&nBsH[kk1 * BS_STRIDE + x4]) = hi;
            *reinterpret_cast<uint4*>(&nBsL[kk1 * BS_STRIDE + x4]) = lo;
            __syncthreads();
        }
    }

#pragma unroll
    for (int im = 0; im < 2; im++) {
        int b = wm + im * 16 + gid;
        int r0 = t * 128 + b, r1 = r0 + 8;
        float m0 = mask[r0], m1 = mask[r1];
#pragma unroll
        for (int in = 0; in < 4; in++) {
            int n = col0 + wn + in * 8 + 2 * tig;
            float bz0 = bias[n], bz1 = bias[n + 1];
            Cout[(size_t)r0 * CODES_ + n]     = fmaxf(C[im][in][0] * m0 + bz0, 0.f);
            Cout[(size_t)r0 * CODES_ + n + 1] = fmaxf(C[im][in][1] * m0 + bz1, 0.f);
            Cout[(size_t)r1 * CODES_ + n]     = fmaxf(C[im][in][2] * m1 + bz0, 0.f);
            Cout[(size_t)r1 * CODES_ + n + 1] = fmaxf(C[im][in][3] * m1 + bz1, 0.f);
        }
    }
}

// ---------------------------------------------------------------------------
__global__ __launch_bounds__(256)
void softmax_kernel(float* __restrict__ out)
{
    __shared__ float red[256];
    const int row = blockIdx.x;
    const int tid = threadIdx.x;
    float* p = out + (size_t)row * CODES_;

    float v[4];
    float m = -1e30f;
#pragma unroll
    for (int i = 0; i < 4; i++) {
        v[i] = p[tid + i * 256];
        m = fmaxf(m, v[i]);
    }
    red[tid] = m;
    __syncthreads();
    for (int s = 128; s > 0; s >>= 1) {
        if (tid < s) red[tid] = fmaxf(red[tid], red[tid + s]);
        __syncthreads();
    }
    m = red[0];
    __syncthreads();

    float sum = 0.f;
#pragma unroll
    for (int i = 0; i < 4; i++) {
        v[i] = __expf(v[i] - m);
        sum += v[i];
    }
    red[tid] = sum;
    __syncthreads();
    for (int s = 128; s > 0; s >>= 1) {
        if (tid < s) red[tid] += red[tid + s];
        __syncthreads();
    }
    float inv = 1.f / red[0];
#pragma unroll
    for (int i = 0; i < 4; i++) p[tid + i * 256] = v[i] * inv;
}

// ---------------------------------------------------------------------------
extern "C" void kernel_launch(void* const* d_in, const int* in_sizes, int n_in,
                              void* d_out, int out_size)
{
    const float* x       = (const float*)d_in[0];
    const float* mask    = (const float*)d_in[1];
    const float* W_in    = (const float*)d_in[2];
    const float* W_rec   = (const float*)d_in[3];
    const float* b_lstm  = (const float*)d_in[4];
    const float* W_dense = (const float*)d_in[5];
    const float* b_dense = (const float*)d_in[6];
    float* out = (float*)d_out;

    const int smem_xz    = 2 * XZ_STAGE * 4;
    const int smem_dense = 2 * DN_STAGE * 4;
    const int smem_lstm  = (2 * 32 * WKST + 2 * HBUF + 32 * CST + 8 * 64) * 4;
    static int attr_set = 0;
    if (!attr_set) {
        cudaFuncSetAttribute(gemm_xz_tc,
                             cudaFuncAttributeMaxDynamicSharedMemorySize, smem_xz);
        cudaFuncSetAttribute(gemm_dense_tc,
                             cudaFuncAttributeMaxDynamicSharedMemorySize, smem_dense);
        cudaFuncSetAttribute(lstm_tc_kernel,
                             cudaFuncAttributeMaxDynamicSharedMemorySize, smem_lstm);
        attr_set = 1;
    }

    init_kernel<<<(U_ * B_ + 255) / 256, 256>>>();

    {   // xz = x @ W_in + b  (TC 3xTF32, transposed output)
        dim3 grid(G_ / 128, T_);
        gemm_xz_tc<<<grid, 512, smem_xz>>>(x, W_in, b_lstm);
    }

    lstm_tc_kernel<<<NBLK, 256, smem_lstm>>>(W_rec);

    {   // dense + mask + relu (TC 3xTF32, pre-split A planes)
        dim3 grid(CODES_ / 128, T_);
        gemm_dense_tc<<<grid, 512, smem_dense>>>(W_dense, b_dense, mask, out);
    }

    softmax_kernel<<<T_ * B_, 256>>>(out);
}

// round 8
// speedup vs baseline: 1.3324x; 1.3324x over previous
#include <cuda_runtime.h>
#include <cuda_bf16.h>
#include <math.h>
#include <stdint.h>

#define T_     256
#define B_     128
#define F_     1024
#define U_     512
#define UP     256    // U/2 pairs
#define G_     2048   // 4*U
#define CODES_ 1024
#define NBLK   128

// Scratch (module-scope device allocations, permitted)
__device__ float    g_xz[(size_t)T_ * G_ * B_];    // [t][c][b]  c = gate*512+u
__device__ float    g_hseq[(size_t)T_ * U_ * B_];  // [t][u][b] fp32 (for dense)
__device__ uint32_t g_hpH[(size_t)T_ * UP * B_];   // [t][u'][b] bf16-hi pairs
__device__ uint32_t g_hpL[(size_t)T_ * UP * B_];   // [t][u'][b] bf16-lo pairs
__device__ uint32_t g_h0p[UP * B_];                // zero pairs
__device__ unsigned g_bar;

// ---------------------------------------------------------------------------
__device__ __forceinline__ uint32_t f2t(float x) {
    uint32_t r; asm("cvt.rna.tf32.f32 %0, %1;" : "=r"(r) : "f"(x)); return r;
}
__device__ __forceinline__ void split4(float4 v, uint4& hi, uint4& lo) {
    hi.x = f2t(v.x); hi.y = f2t(v.y); hi.z = f2t(v.z); hi.w = f2t(v.w);
    lo.x = f2t(v.x - __uint_as_float(hi.x));
    lo.y = f2t(v.y - __uint_as_float(hi.y));
    lo.z = f2t(v.z - __uint_as_float(hi.z));
    lo.w = f2t(v.w - __uint_as_float(hi.w));
}
__device__ __forceinline__ void mma_tf32(float* d,
                                         const uint32_t* a, const uint32_t* b) {
    asm volatile("mma.sync.aligned.m16n8k8.row.col.f32.tf32.tf32.f32 "
        "{%0,%1,%2,%3}, {%4,%5,%6,%7}, {%8,%9}, {%0,%1,%2,%3};"
        : "+f"(d[0]), "+f"(d[1]), "+f"(d[2]), "+f"(d[3])
        : "r"(a[0]), "r"(a[1]), "r"(a[2]), "r"(a[3]), "r"(b[0]), "r"(b[1]));
}
__device__ __forceinline__ void mma_bf16(float* d,
                                         const uint32_t* a, const uint32_t* b) {
    asm volatile("mma.sync.aligned.m16n8k16.row.col.f32.bf16.bf16.f32 "
        "{%0,%1,%2,%3}, {%4,%5,%6,%7}, {%8,%9}, {%0,%1,%2,%3};"
        : "+f"(d[0]), "+f"(d[1]), "+f"(d[2]), "+f"(d[3])
        : "r"(a[0]), "r"(a[1]), "r"(a[2]), "r"(a[3]), "r"(b[0]), "r"(b[1]));
}
__device__ __forceinline__ uint32_t pack_bf16(float a, float b) {
    __nv_bfloat16 ba = __float2bfloat16(a), bb = __float2bfloat16(b);
    return (uint32_t)__bfloat16_as_ushort(ba) |
           ((uint32_t)__bfloat16_as_ushort(bb) << 16);
}

// ---------------------------------------------------------------------------
__global__ void init_kernel() {
    int i = blockIdx.x * blockDim.x + threadIdx.x;
    if (i < UP * B_) g_h0p[i] = 0u;
    if (i == 0) g_bar = 0u;
}

// ---------------------------------------------------------------------------
// GEMM 1 (TC 3xTF32, double-buffered): xz = x @ W_in + b -> g_xz[t][col][b]
// ---------------------------------------------------------------------------
#define AS_STRIDE 36
#define BS_STRIDE 136
#define XZ_STAGE  (2 * 128 * AS_STRIDE + 2 * 32 * BS_STRIDE)
#define DN_STAGE  (4 * 32 * BS_STRIDE)

__global__ __launch_bounds__(512)
void gemm_xz_tc(const float* __restrict__ A,
                const float* __restrict__ Bm,
                const float* __restrict__ bias)
{
    extern __shared__ uint32_t smx[];

    const int tid  = threadIdx.x;
    const int lane = tid & 31, w = tid >> 5;
    const int gid  = lane >> 2, tig = lane & 3;
    const int wm   = (w >> 2) * 32, wn = (w & 3) * 32;
    const int t    = blockIdx.y;
    const int row0 = t * 128;
    const int col0 = blockIdx.x * 128;

    const int arow0 = tid >> 3,        ak4 = (tid & 7) << 2;
    const int arow1 = (tid + 512) >> 3;
    const int bkk0 = tid >> 5,         bn4 = (tid & 31) << 2;
    const int bkk1 = (tid + 512) >> 5;

    float C[2][4][4];
#pragma unroll
    for (int im = 0; im < 2; im++)
#pragma unroll
        for (int in = 0; in < 4; in++)
#pragma unroll
            for (int r = 0; r < 4; r++) C[im][in][r] = 0.f;

    float4 pa0, pa1, pb0, pb1;
    pa0 = *reinterpret_cast<const float4*>(&A[(size_t)(row0 + arow0) * F_ + ak4]);
    pa1 = *reinterpret_cast<const float4*>(&A[(size_t)(row0 + arow1) * F_ + ak4]);
    pb0 = *reinterpret_cast<const float4*>(&Bm[(size_t)bkk0 * G_ + col0 + bn4]);
    pb1 = *reinterpret_cast<const float4*>(&Bm[(size_t)bkk1 * G_ + col0 + bn4]);
    {
        uint32_t* AsH = smx;
        uint32_t* AsL = AsH + 128 * AS_STRIDE;
        uint32_t* BsH = AsL + 128 * AS_STRIDE;
        uint32_t* BsL = BsH + 32 * BS_STRIDE;
        uint4 hi, lo;
        split4(pa0, hi, lo);
        *reinterpret_cast<uint4*>(&AsH[arow0 * AS_STRIDE + ak4]) = hi;
        *reinterpret_cast<uint4*>(&AsL[arow0 * AS_STRIDE + ak4]) = lo;
        split4(pa1, hi, lo);
        *reinterpret_cast<uint4*>(&AsH[arow1 * AS_STRIDE + ak4]) = hi;
        *reinterpret_cast<uint4*>(&AsL[arow1 * AS_STRIDE + ak4]) = lo;
        split4(pb0, hi, lo);
        *reinterpret_cast<uint4*>(&BsH[bkk0 * BS_STRIDE + bn4]) = hi;
        *reinterpret_cast<uint4*>(&BsL[bkk0 * BS_STRIDE + bn4]) = lo;
        split4(pb1, hi, lo);
        *reinterpret_cast<uint4*>(&BsH[bkk1 * BS_STRIDE + bn4]) = hi;
        *reinterpret_cast<uint4*>(&BsL[bkk1 * BS_STRIDE + bn4]) = lo;
    }
    __syncthreads();

    for (int k0 = 0; k0 < F_; k0 += 32) {
        const int s = (k0 >> 5) & 1;
        uint32_t* AsH = smx + s * XZ_STAGE;
        uint32_t* AsL = AsH + 128 * AS_STRIDE;
        uint32_t* BsH = AsL + 128 * AS_STRIDE;
        uint32_t* BsL = BsH + 32 * BS_STRIDE;
        const bool more = (k0 + 32 < F_);

        if (more) {
            pa0 = *reinterpret_cast<const float4*>(
                &A[(size_t)(row0 + arow0) * F_ + k0 + 32 + ak4]);
            pa1 = *reinterpret_cast<const float4*>(
                &A[(size_t)(row0 + arow1) * F_ + k0 + 32 + ak4]);
            pb0 = *reinterpret_cast<const float4*>(
                &Bm[(size_t)(k0 + 32 + bkk0) * G_ + col0 + bn4]);
            pb1 = *reinterpret_cast<const float4*>(
                &Bm[(size_t)(k0 + 32 + bkk1) * G_ + col0 + bn4]);
        }

#pragma unroll
        for (int k8 = 0; k8 < 4; k8++) {
            uint32_t aH[2][4], aL[2][4], bH[4][2], bL[4][2];
#pragma unroll
            for (int im = 0; im < 2; im++) {
                int m = wm + im * 16;
                int p0 = (m + gid) * AS_STRIDE + k8 * 8 + tig;
                int p1 = (m + gid + 8) * AS_STRIDE + k8 * 8 + tig;
                aH[im][0] = AsH[p0];     aH[im][1] = AsH[p1];
                aH[im][2] = AsH[p0 + 4]; aH[im][3] = AsH[p1 + 4];
                aL[im][0] = AsL[p0];     aL[im][1] = AsL[p1];
                aL[im][2] = AsL[p0 + 4]; aL[im][3] = AsL[p1 + 4];
            }
#pragma unroll
            for (int in = 0; in < 4; in++) {
                int n = wn + in * 8 + gid;
                int kb = k8 * 8 + tig;
                bH[in][0] = BsH[kb * BS_STRIDE + n];
                bH[in][1] = BsH[(kb + 4) * BS_STRIDE + n];
                bL[in][0] = BsL[kb * BS_STRIDE + n];
                bL[in][1] = BsL[(kb + 4) * BS_STRIDE + n];
            }
#pragma unroll
            for (int im = 0; im < 2; im++)
#pragma unroll
                for (int in = 0; in < 4; in++) {
                    mma_tf32(C[im][in], aH[im], bH[in]);
                    mma_tf32(C[im][in], aL[im], bH[in]);
                    mma_tf32(C[im][in], aH[im], bL[in]);
                }
        }

        if (more) {
            uint32_t* nAsH = smx + (s ^ 1) * XZ_STAGE;
            uint32_t* nAsL = nAsH + 128 * AS_STRIDE;
            uint32_t* nBsH = nAsL + 128 * AS_STRIDE;
            uint32_t* nBsL = nBsH + 32 * BS_STRIDE;
            uint4 hi, lo;
            split4(pa0, hi, lo);
            *reinterpret_cast<uint4*>(&nAsH[arow0 * AS_STRIDE + ak4]) = hi;
            *reinterpret_cast<uint4*>(&nAsL[arow0 * AS_STRIDE + ak4]) = lo;
            split4(pa1, hi, lo);
            *reinterpret_cast<uint4*>(&nAsH[arow1 * AS_STRIDE + ak4]) = hi;
            *reinterpret_cast<uint4*>(&nAsL[arow1 * AS_STRIDE + ak4]) = lo;
            split4(pb0, hi, lo);
            *reinterpret_cast<uint4*>(&nBsH[bkk0 * BS_STRIDE + bn4]) = hi;
            *reinterpret_cast<uint4*>(&nBsL[bkk0 * BS_STRIDE + bn4]) = lo;
            split4(pb1, hi, lo);
            *reinterpret_cast<uint4*>(&nBsH[bkk1 * BS_STRIDE + bn4]) = hi;
            *reinterpret_cast<uint4*>(&nBsL[bkk1 * BS_STRIDE + bn4]) = lo;
            __syncthreads();
        }
    }

#pragma unroll
    for (int im = 0; im < 2; im++) {
        int b = wm + im * 16 + gid;
#pragma unroll
        for (int in = 0; in < 4; in++) {
            int n = col0 + wn + in * 8 + 2 * tig;
            float bz0 = bias[n], bz1 = bias[n + 1];
            size_t p = ((size_t)t * G_ + n) * B_;
            g_xz[p + b]           = C[im][in][0] + bz0;
            g_xz[p + B_ + b]      = C[im][in][1] + bz1;
            g_xz[p + b + 8]       = C[im][in][2] + bz0;
            g_xz[p + B_ + b + 8]  = C[im][in][3] + bz1;
        }
    }
}

// ---------------------------------------------------------------------------
// Persistent LSTM, bf16 2-split tensor cores, z^T formulation.
// 32 unit-blocks (16 units = 64 gate-cols) x 4 batch-blocks (32 batch).
// z^T[c=64][b=32] = W^T[c][k=512] @ h[k][b];  A = W (SMEM, [m=c][k-pair]),
// B = h (global bf16 pairs [u'][b], staged [k-pair][b]).
// ---------------------------------------------------------------------------
#define WST   260   // u32 stride of Ws rows (k' = 256 + pad)
#define HST2  40    // u32 stride of staged h rows (b = 32 + pad 8 -> conflict-free)
#define STSH  36
#define HCH   (64 * HST2)          // u32 per plane per buffer (64 k'-rows)

__global__ __launch_bounds__(256)
void lstm_tc_kernel(const float* __restrict__ W_rec)
{
    extern __shared__ uint32_t sm[];
    uint32_t* WsH = sm;                        // [64][WST]
    uint32_t* WsL = WsH + 64 * WST;
    uint32_t* Hsb = WsL + 64 * WST;            // [2 buf][2 planes][64][HST2]
    float* stash  = reinterpret_cast<float*>(Hsb + 2 * 2 * HCH);  // [64][STSH]
    float* cs     = stash + 64 * STSH;         // [16][32]

    const int tid  = threadIdx.x;
    const int lane = tid & 31, wrp = tid >> 5;
    const int gid  = lane >> 2, tig = lane & 3;
    const int wm   = (wrp & 3) * 16;           // gate-col tile
    const int wnb  = (wrp >> 2) * 16;          // batch tile (2 n8 tiles)
    const int ub   = blockIdx.x >> 2;          // 0..31 -> units [ub*16, +16)
    const int bb   = blockIdx.x & 3;
    const int bg0  = bb * 32;

    // Load + split W slice once: Ws[c][k'] = bf16-pair of W_rec[2k',2k'+1][col(c)]
    for (int idx = tid; idx < 64 * 256; idx += 256) {
        int kp = idx & 255, c = idx >> 8;
        int gc = (c >> 4) * U_ + ub * 16 + (c & 15);
        float w0 = W_rec[(size_t)(2 * kp) * G_ + gc];
        float w1 = W_rec[(size_t)(2 * kp + 1) * G_ + gc];
        __nv_bfloat16 h0 = __float2bfloat16(w0);
        __nv_bfloat16 h1 = __float2bfloat16(w1);
        float l0 = w0 - __bfloat162float(h0);
        float l1 = w1 - __bfloat162float(h1);
        WsH[c * WST + kp] = (uint32_t)__bfloat16_as_ushort(h0) |
                            ((uint32_t)__bfloat16_as_ushort(h1) << 16);
        WsL[c * WST + kp] = pack_bf16(l0, l1);
    }
    for (int i = tid; i < 16 * 32; i += 256) cs[i] = 0.f;
    __syncthreads();

    // stage coords: 2 uint4 per plane per thread per chunk (64 k'-rows x 32 b)
    const int sr0 = tid >> 3, sb4 = (tid & 7) << 2;   // rows sr0, sr0+32

    const int eb = tid & 31, eu2 = tid >> 5;           // epilogue: pair eu2, batch eb

    for (int t = 0; t < T_; t++) {
        const uint32_t* hpH = (t == 0) ? g_h0p : (g_hpH + (size_t)(t - 1) * UP * B_);
        const uint32_t* hpL = (t == 0) ? g_h0p : (g_hpL + (size_t)(t - 1) * UP * B_);
        const float* xz_t = g_xz + (size_t)t * G_ * B_;

        // prefetch epilogue xz (4 gates x 2 units), coalesced over b
        float xzv[4][2];
#pragma unroll
        for (int g = 0; g < 4; g++)
#pragma unroll
            for (int j = 0; j < 2; j++)
                xzv[g][j] = xz_t[(size_t)(g * U_ + ub * 16 + 2 * eu2 + j) * B_ + bg0 + eb];

        float C[2][4];
#pragma unroll
        for (int in = 0; in < 2; in++)
#pragma unroll
            for (int r = 0; r < 4; r++) C[in][r] = 0.f;

        // stage chunk 0
        uint4 pfh0, pfh1, pfl0, pfl1;
        pfh0 = *reinterpret_cast<const uint4*>(&hpH[(size_t)sr0 * B_ + bg0 + sb4]);
        pfh1 = *reinterpret_cast<const uint4*>(&hpH[(size_t)(sr0 + 32) * B_ + bg0 + sb4]);
        pfl0 = *reinterpret_cast<const uint4*>(&hpL[(size_t)sr0 * B_ + bg0 + sb4]);
        pfl1 = *reinterpret_cast<const uint4*>(&hpL[(size_t)(sr0 + 32) * B_ + bg0 + sb4]);
        {
            uint32_t* bH = Hsb;
            uint32_t* bL = Hsb + HCH;
            *reinterpret_cast<uint4*>(&bH[sr0 * HST2 + sb4]) = pfh0;
            *reinterpret_cast<uint4*>(&bH[(sr0 + 32) * HST2 + sb4]) = pfh1;
            *reinterpret_cast<uint4*>(&bL[sr0 * HST2 + sb4]) = pfl0;
            *reinterpret_cast<uint4*>(&bL[(sr0 + 32) * HST2 + sb4]) = pfl1;
        }
        __syncthreads();

        for (int kc = 0; kc < 4; kc++) {
            uint32_t* bH = Hsb + (kc & 1) * 2 * HCH;
            uint32_t* bL = bH + HCH;
            const bool more = (kc < 3);

            if (more) {
                const uint32_t* nH = hpH + (size_t)(kc + 1) * 64 * B_;
                const uint32_t* nL = hpL + (size_t)(kc + 1) * 64 * B_;
                pfh0 = *reinterpret_cast<const uint4*>(&nH[(size_t)sr0 * B_ + bg0 + sb4]);
                pfh1 = *reinterpret_cast<const uint4*>(&nH[(size_t)(sr0 + 32) * B_ + bg0 + sb4]);
                pfl0 = *reinterpret_cast<const uint4*>(&nL[(size_t)sr0 * B_ + bg0 + sb4]);
                pfl1 = *reinterpret_cast<const uint4*>(&nL[(size_t)(sr0 + 32) * B_ + bg0 + sb4]);
            }

#pragma unroll
            for (int ks = 0; ks < 8; ks++) {        // k16 steps within chunk
                const int kb = ks * 8;
                uint32_t aH[4], aL[4];
                {
                    int p0 = (wm + gid) * WST + kc * 64 + kb + tig;
                    int p1 = (wm + gid + 8) * WST + kc * 64 + kb + tig;
                    aH[0] = WsH[p0];     aH[1] = WsH[p1];
                    aH[2] = WsH[p0 + 4]; aH[3] = WsH[p1 + 4];
                    aL[0] = WsL[p0];     aL[1] = WsL[p1];
                    aL[2] = WsL[p0 + 4]; aL[3] = WsL[p1 + 4];
                }
#pragma unroll
                for (int in = 0; in < 2; in++) {
                    int n = wnb + in * 8 + gid;
                    uint32_t bHf[2], bLf[2];
                    bHf[0] = bH[(kb + tig) * HST2 + n];
                    bHf[1] = bH[(kb + tig + 4) * HST2 + n];
                    bLf[0] = bL[(kb + tig) * HST2 + n];
                    bLf[1] = bL[(kb + tig + 4) * HST2 + n];
                    mma_bf16(C[in], aH, bHf);
                    mma_bf16(C[in], aL, bHf);
                    mma_bf16(C[in], aH, bLf);
                }
            }

            if (more) {
                uint32_t* nbH = Hsb + ((kc + 1) & 1) * 2 * HCH;
                uint32_t* nbL = nbH + HCH;
                *reinterpret_cast<uint4*>(&nbH[sr0 * HST2 + sb4]) = pfh0;
                *reinterpret_cast<uint4*>(&nbH[(sr0 + 32) * HST2 + sb4]) = pfh1;
                *reinterpret_cast<uint4*>(&nbL[sr0 * HST2 + sb4]) = pfl0;
                *reinterpret_cast<uint4*>(&nbL[(sr0 + 32) * HST2 + sb4]) = pfl1;
                __syncthreads();
            }
        }

        // C frags -> stash[c][b]
#pragma unroll
        for (int in = 0; in < 2; in++) {
            int n0 = wnb + in * 8 + 2 * tig;
            float2 v0 = { C[in][0], C[in][1] };
            float2 v1 = { C[in][2], C[in][3] };
            *reinterpret_cast<float2*>(&stash[(wm + gid) * STSH + n0])     = v0;
            *reinterpret_cast<float2*>(&stash[(wm + gid + 8) * STSH + n0]) = v1;
        }
        __syncthreads();

        // epilogue: 2 units x 1 batch per thread
        float hv[2];
#pragma unroll
        for (int j = 0; j < 2; j++) {
            int ul = 2 * eu2 + j;
            float zi = stash[(0 * 16 + ul) * STSH + eb] + xzv[0][j];
            float zf = stash[(1 * 16 + ul) * STSH + eb] + xzv[1][j];
            float zg = stash[(2 * 16 + ul) * STSH + eb] + xzv[2][j];
            float zo = stash[(3 * 16 + ul) * STSH + eb] + xzv[3][j];
            float ig = 1.f / (1.f + __expf(-zi));
            float fg = 1.f / (1.f + __expf(-zf));
            float gg = 1.f - 2.f / (1.f + __expf(2.f * zg));
            float og = 1.f / (1.f + __expf(-zo));
            float cn = fg * cs[ul * 32 + eb] + ig * gg;
            cs[ul * 32 + eb] = cn;
            hv[j] = og * (1.f - 2.f / (1.f + __expf(2.f * cn)));
        }

        // write fp32 h (for dense) and bf16 hi/lo pairs (for recurrence)
        float* h_out = g_hseq + (size_t)t * U_ * B_;
        h_out[(size_t)(ub * 16 + 2 * eu2) * B_ + bg0 + eb]     = hv[0];
        h_out[(size_t)(ub * 16 + 2 * eu2 + 1) * B_ + bg0 + eb] = hv[1];
        __nv_bfloat16 b0 = __float2bfloat16(hv[0]);
        __nv_bfloat16 b1 = __float2bfloat16(hv[1]);
        uint32_t hiP = (uint32_t)__bfloat16_as_ushort(b0) |
                       ((uint32_t)__bfloat16_as_ushort(b1) << 16);
        uint32_t loP = pack_bf16(hv[0] - __bfloat162float(b0),
                                 hv[1] - __bfloat162float(b1));
        size_t pq = (size_t)t * UP * B_ + (size_t)(ub * 8 + eu2) * B_ + bg0 + eb;
        g_hpH[pq] = hiP;
        g_hpL[pq] = loP;

        // software grid barrier
        __threadfence();
        __syncthreads();
        if (tid == 0) {
            atomicAdd(&g_bar, 1u);
            unsigned tgt = (unsigned)(NBLK * (t + 1));
            while (*((volatile unsigned*)&g_bar) < tgt) { }
            __threadfence();
        }
        __syncthreads();
    }
}

// ---------------------------------------------------------------------------
// GEMM 3 (TC 3xTF32, double-buffered): out = relu(mask*(h@W_dense)+b_dense)
// A from fp32 g_hseq [t][u][b]
// ---------------------------------------------------------------------------
__global__ __launch_bounds__(512)
void gemm_dense_tc(const float* __restrict__ Bm,
                   const float* __restrict__ bias,
                   const float* __restrict__ mask,
                   float* __restrict__ Cout)
{
    extern __shared__ uint32_t smx[];

    const int tid  = threadIdx.x;
    const int lane = tid & 31, w = tid >> 5;
    const int gid  = lane >> 2, tig = lane & 3;
    const int wm   = (w >> 2) * 32, wn = (w & 3) * 32;
    const int t    = blockIdx.y;
    const int col0 = blockIdx.x * 128;
    const float* Ablk = g_hseq + (size_t)t * U_ * B_;

    const int kk0 = tid >> 5, x4 = (tid & 31) << 2;
    const int kk1 = (tid + 512) >> 5;

    float C[2][4][4];
#pragma unroll
    for (int im = 0; im < 2; im++)
#pragma unroll
        for (int in = 0; in < 4; in++)
#pragma unroll
            for (int r = 0; r < 4; r++) C[im][in][r] = 0.f;

    float4 pa0, pa1, pb0, pb1;
    pa0 = *reinterpret_cast<const float4*>(&Ablk[(size_t)kk0 * B_ + x4]);
    pa1 = *reinterpret_cast<const float4*>(&Ablk[(size_t)kk1 * B_ + x4]);
    pb0 = *reinterpret_cast<const float4*>(&Bm[(size_t)kk0 * CODES_ + col0 + x4]);
    pb1 = *reinterpret_cast<const float4*>(&Bm[(size_t)kk1 * CODES_ + col0 + x4]);
    {
        uint32_t* AsH = smx;
        uint32_t* AsL = AsH + 32 * BS_STRIDE;
        uint32_t* BsH = AsL + 32 * BS_STRIDE;
        uint32_t* BsL = BsH + 32 * BS_STRIDE;
        uint4 hi, lo;
        split4(pa0, hi, lo);
        *reinterpret_cast<uint4*>(&AsH[kk0 * BS_STRIDE + x4]) = hi;
        *reinterpret_cast<uint4*>(&AsL[kk0 * BS_STRIDE + x4]) = lo;
        split4(pa1, hi, lo);
        *reinterpret_cast<uint4*>(&AsH[kk1 * BS_STRIDE + x4]) = hi;
        *reinterpret_cast<uint4*>(&AsL[kk1 * BS_STRIDE + x4]) = lo;
        split4(pb0, hi, lo);
        *reinterpret_cast<uint4*>(&BsH[kk0 * BS_STRIDE + x4]) = hi;
        *reinterpret_cast<uint4*>(&BsL[kk0 * BS_STRIDE + x4]) = lo;
        split4(pb1, hi, lo);
        *reinterpret_cast<uint4*>(&BsH[kk1 * BS_STRIDE + x4]) = hi;
        *reinterpret_cast<uint4*>(&BsL[kk1 * BS_STRIDE + x4]) = lo;
    }
    __syncthreads();

    for (int k0 = 0; k0 < U_; k0 += 32) {
        const int s = (k0 >> 5) & 1;
        uint32_t* AsH = smx + s * DN_STAGE;
        uint32_t* AsL = AsH + 32 * BS_STRIDE;
        uint32_t* BsH = AsL + 32 * BS_STRIDE;
        uint32_t* BsL = BsH + 32 * BS_STRIDE;
        const bool more = (k0 + 32 < U_);

        if (more) {
            pa0 = *reinterpret_cast<const float4*>(
                &Ablk[(size_t)(k0 + 32 + kk0) * B_ + x4]);
            pa1 = *reinterpret_cast<const float4*>(
                &Ablk[(size_t)(k0 + 32 + kk1) * B_ + x4]);
            pb0 = *reinterpret_cast<const float4*>(
                &Bm[(size_t)(k0 + 32 + kk0) * CODES_ + col0 + x4]);
            pb1 = *reinterpret_cast<const float4*>(
                &Bm[(size_t)(k0 + 32 + kk1) * CODES_ + col0 + x4]);
        }

#pragma unroll
        for (int k8 = 0; k8 < 4; k8++) {
            uint32_t aH[2][4], aL[2][4], bH[4][2], bL[4][2];
#pragma unroll
            for (int im = 0; im < 2; im++) {
                int m = wm + im * 16 + gid;
                int kb = k8 * 8 + tig;
                int p0 = kb * BS_STRIDE + m;
                aH[im][0] = AsH[p0];      aH[im][1] = AsH[p0 + 8];
                aH[im][2] = AsH[p0 + 4 * BS_STRIDE];
                aH[im][3] = AsH[p0 + 4 * BS_STRIDE + 8];
                aL[im][0] = AsL[p0];      aL[im][1] = AsL[p0 + 8];
                aL[im][2] = AsL[p0 + 4 * BS_STRIDE];
                aL[im][3] = AsL[p0 + 4 * BS_STRIDE + 8];
            }
#pragma unroll
            for (int in = 0; in < 4; in++) {
                int n = wn + in * 8 + gid;
                int kb = k8 * 8 + tig;
                bH[in][0] = BsH[kb * BS_STRIDE + n];
                bH[in][1] = BsH[(kb + 4) * BS_STRIDE + n];
                bL[in][0] = BsL[kb * BS_STRIDE + n];
                bL[in][1] = BsL[(kb + 4) * BS_STRIDE + n];
            }
#pragma unroll
            for (int im = 0; im < 2; im++)
#pragma unroll
                for (int in = 0; in < 4; in++) {
                    mma_tf32(C[im][in], aH[im], bH[in]);
                    mma_tf32(C[im][in], aL[im], bH[in]);
                    mma_tf32(C[im][in], aH[im], bL[in]);
                }
        }

        if (more) {
            uint32_t* nAsH = smx + (s ^ 1) * DN_STAGE;
            uint32_t* nAsL = nAsH + 32 * BS_STRIDE;
            uint32_t* nBsH = nAsL + 32 * BS_STRIDE;
            uint32_t* nBsL = nBsH + 32 * BS_STRIDE;
            uint4 hi, lo;
            split4(pa0, hi, lo);
            *reinterpret_cast<uint4*>(&nAsH[kk0 * BS_STRIDE + x4]) = hi;
            *reinterpret_cast<uint4*>(&nAsL[kk0 * BS_STRIDE + x4]) = lo;
            split4(pa1, hi, lo);
            *reinterpret_cast<uint4*>(&nAsH[kk1 * BS_STRIDE + x4]) = hi;
            *reinterpret_cast<uint4*>(&nAsL[kk1 * BS_STRIDE + x4]) = lo;
            split4(pb0, hi, lo);
            *reinterpret_cast<uint4*>(&nBsH[kk0 * BS_STRIDE + x4]) = hi;
            *reinterpret_cast<uint4*>(&nBsL[kk0 * BS_STRIDE + x4]) = lo;
            split4(pb1, hi, lo);
            *reinterpret_cast<uint4*>(&nBsH[kk1 * BS_STRIDE + x4]) = hi;
            *reinterpret_cast<uint4*>(&nBsL[kk1 * BS_STRIDE + x4]) = lo;
            __syncthreads();
        }
    }

#pragma unroll
    for (int im = 0; im < 2; im++) {
        int b = wm + im * 16 + gid;
        int r0 = t * 128 + b, r1 = r0 + 8;
        float m0 = mask[r0], m1 = mask[r1];
#pragma unroll
        for (int in = 0; in < 4; in++) {
            int n = col0 + wn + in * 8 + 2 * tig;
            float bz0 = bias[n], bz1 = bias[n + 1];
            Cout[(size_t)r0 * CODES_ + n]     = fmaxf(C[im][in][0] * m0 + bz0, 0.f);
            Cout[(size_t)r0 * CODES_ + n + 1] = fmaxf(C[im][in][1] * m0 + bz1, 0.f);
            Cout[(size_t)r1 * CODES_ + n]     = fmaxf(C[im][in][2] * m1 + bz0, 0.f);
            Cout[(size_t)r1 * CODES_ + n + 1] = fmaxf(C[im][in][3] * m1 + bz1, 0.f);
        }
    }
}

// ---------------------------------------------------------------------------
__global__ __launch_bounds__(256)
void softmax_kernel(float* __restrict__ out)
{
    __shared__ float red[256];
    const int row = blockIdx.x;
    const int tid = threadIdx.x;
    float* p = out + (size_t)row * CODES_;

    float v[4];
    float m = -1e30f;
#pragma unroll
    for (int i = 0; i < 4; i++) {
        v[i] = p[tid + i * 256];
        m = fmaxf(m, v[i]);
    }
    red[tid] = m;
    __syncthreads();
    for (int s = 128; s > 0; s >>= 1) {
        if (tid < s) red[tid] = fmaxf(red[tid], red[tid + s]);
        __syncthreads();
    }
    m = red[0];
    __syncthreads();

    float sum = 0.f;
#pragma unroll
    for (int i = 0; i < 4; i++) {
        v[i] = __expf(v[i] - m);
        sum += v[i];
    }
    red[tid] = sum;
    __syncthreads();
    for (int s = 128; s > 0; s >>= 1) {
        if (tid < s) red[tid] += red[tid + s];
        __syncthreads();
    }
    float inv = 1.f / red[0];
#pragma unroll
    for (int i = 0; i < 4; i++) p[tid + i * 256] = v[i] * inv;
}

// ---------------------------------------------------------------------------
extern "C" void kernel_launch(void* const* d_in, const int* in_sizes, int n_in,
                              void* d_out, int out_size)
{
    const float* x       = (const float*)d_in[0];
    const float* mask    = (const float*)d_in[1];
    const float* W_in    = (const float*)d_in[2];
    const float* W_rec   = (const float*)d_in[3];
    const float* b_lstm  = (const float*)d_in[4];
    const float* W_dense = (const float*)d_in[5];
    const float* b_dense = (const float*)d_in[6];
    float* out = (float*)d_out;

    const int smem_xz    = 2 * XZ_STAGE * 4;
    const int smem_dense = 2 * DN_STAGE * 4;
    const int smem_lstm  = (2 * 64 * WST + 2 * 2 * HCH + 64 * STSH + 16 * 32) * 4;
    static int attr_set = 0;
    if (!attr_set) {
        cudaFuncSetAttribute(gemm_xz_tc,
                             cudaFuncAttributeMaxDynamicSharedMemorySize, smem_xz);
        cudaFuncSetAttribute(gemm_dense_tc,
                             cudaFuncAttributeMaxDynamicSharedMemorySize, smem_dense);
        cudaFuncSetAttribute(lstm_tc_kernel,
                             cudaFuncAttributeMaxDynamicSharedMemorySize, smem_lstm);
        attr_set = 1;
    }

    init_kernel<<<(UP * B_ + 255) / 256, 256>>>();

    {   // xz = x @ W_in + b  (TC 3xTF32, transposed output)
        dim3 grid(G_ / 128, T_);
        gemm_xz_tc<<<grid, 512, smem_xz>>>(x, W_in, b_lstm);
    }

    lstm_tc_kernel<<<NBLK, 256, smem_lstm>>>(W_rec);

    {   // dense + mask + relu (TC 3xTF32)
        dim3 grid(CODES_ / 128, T_);
        gemm_dense_tc<<<grid, 512, smem_dense>>>(W_dense, b_dense, mask, out);
    }

    softmax_kernel<<<T_ * B_, 256>>>(out);
}

// round 9
// speedup vs baseline: 1.6912x; 1.2693x over previous
#include <cuda_runtime.h>
#include <cuda_bf16.h>
#include <math.h>
#include <stdint.h>

#define T_     256
#define B_     128
#define F_     1024
#define U_     512
#define UP     256    // U/2 pairs
#define G_     2048   // 4*U
#define CODES_ 1024
#define NBLK   128

// Scratch (module-scope device allocations, permitted)
__device__ float    g_xz[(size_t)T_ * G_ * B_];    // [t][c][b]  c = gate*512+u
__device__ uint32_t g_hpH[(size_t)T_ * UP * B_];   // [t][u'][b] bf16-hi pairs
__device__ uint32_t g_hpL[(size_t)T_ * UP * B_];   // [t][u'][b] bf16-lo pairs
__device__ uint32_t g_h0p[UP * B_];                // zero pairs
__device__ unsigned g_bar;

// ---------------------------------------------------------------------------
__device__ __forceinline__ void mma_bf16(float* d,
                                         const uint32_t* a, const uint32_t* b) {
    asm volatile("mma.sync.aligned.m16n8k16.row.col.f32.bf16.bf16.f32 "
        "{%0,%1,%2,%3}, {%4,%5,%6,%7}, {%8,%9}, {%0,%1,%2,%3};"
        : "+f"(d[0]), "+f"(d[1]), "+f"(d[2]), "+f"(d[3])
        : "r"(a[0]), "r"(a[1]), "r"(a[2]), "r"(a[3]), "r"(b[0]), "r"(b[1]));
}
__device__ __forceinline__ uint32_t pack_bf16(float a, float b) {
    __nv_bfloat16 ba = __float2bfloat16(a), bb = __float2bfloat16(b);
    return (uint32_t)__bfloat16_as_ushort(ba) |
           ((uint32_t)__bfloat16_as_ushort(bb) << 16);
}
// split two floats into bf16 hi-pair and lo-pair
__device__ __forceinline__ void split_pair(float a, float b,
                                           uint32_t& hiP, uint32_t& loP) {
    __nv_bfloat16 ha = __float2bfloat16(a), hb = __float2bfloat16(b);
    hiP = (uint32_t)__bfloat16_as_ushort(ha) |
          ((uint32_t)__bfloat16_as_ushort(hb) << 16);
    loP = pack_bf16(a - __bfloat162float(ha), b - __bfloat162float(hb));
}

// ---------------------------------------------------------------------------
__global__ void init_kernel() {
    int i = blockIdx.x * blockDim.x + threadIdx.x;
    if (i < UP * B_) g_h0p[i] = 0u;
    if (i == 0) g_bar = 0u;
}

// ---------------------------------------------------------------------------
// GEMM 1 (bf16 2-split TC, double-buffered): xz = x @ W_in + b
// output transposed: g_xz[t][col][b]
// As [m=128][k'=16] stride 20; Bs [k'=16][n=128] stride 136 (both hi+lo)
// ---------------------------------------------------------------------------
#define XAST 20
#define NBST 136
#define XZ_STAGE (2 * 128 * XAST + 2 * 16 * NBST)   // u32 per stage
#define DN_STAGE (2 * 16 * NBST + 2 * 16 * NBST)    // A planes + B planes

__global__ __launch_bounds__(512)
void gemm_xz_tc(const float* __restrict__ A,
                const float* __restrict__ Bm,
                const float* __restrict__ bias)
{
    extern __shared__ uint32_t smx[];

    const int tid  = threadIdx.x;
    const int lane = tid & 31, w = tid >> 5;
    const int gid  = lane >> 2, tig = lane & 3;
    const int wm   = (w >> 2) * 32, wn = (w & 3) * 32;
    const int t    = blockIdx.y;
    const int row0 = t * 128;
    const int col0 = blockIdx.x * 128;

    // A staging coords: 2 tasks, each float4 (4 k) of one row
    const int ar0 = tid >> 3,          ak4 = (tid & 7) << 2;
    const int ar1 = (tid + 512) >> 3;
    // B staging coords: 1 task: k-pair row kp, 4 n
    const int bkp = tid >> 5,          bn4 = (tid & 31) << 2;

    float C[2][4][4];
#pragma unroll
    for (int im = 0; im < 2; im++)
#pragma unroll
        for (int in = 0; in < 4; in++)
#pragma unroll
            for (int r = 0; r < 4; r++) C[im][in][r] = 0.f;

    float4 pa0, pa1, pbA, pbB;
    pa0 = *reinterpret_cast<const float4*>(&A[(size_t)(row0 + ar0) * F_ + ak4]);
    pa1 = *reinterpret_cast<const float4*>(&A[(size_t)(row0 + ar1) * F_ + ak4]);
    pbA = *reinterpret_cast<const float4*>(&Bm[(size_t)(2 * bkp) * G_ + col0 + bn4]);
    pbB = *reinterpret_cast<const float4*>(&Bm[(size_t)(2 * bkp + 1) * G_ + col0 + bn4]);

    {
        uint32_t* AsH = smx;
        uint32_t* AsL = AsH + 128 * XAST;
        uint32_t* BsH = AsL + 128 * XAST;
        uint32_t* BsL = BsH + 16 * NBST;
        uint32_t h0, l0, h1, l1;
        split_pair(pa0.x, pa0.y, h0, l0); split_pair(pa0.z, pa0.w, h1, l1);
        *reinterpret_cast<uint2*>(&AsH[ar0 * XAST + (ak4 >> 1)]) = make_uint2(h0, h1);
        *reinterpret_cast<uint2*>(&AsL[ar0 * XAST + (ak4 >> 1)]) = make_uint2(l0, l1);
        split_pair(pa1.x, pa1.y, h0, l0); split_pair(pa1.z, pa1.w, h1, l1);
        *reinterpret_cast<uint2*>(&AsH[ar1 * XAST + (ak4 >> 1)]) = make_uint2(h0, h1);
        *reinterpret_cast<uint2*>(&AsL[ar1 * XAST + (ak4 >> 1)]) = make_uint2(l0, l1);
        uint4 bh, bl;
        split_pair(pbA.x, pbB.x, bh.x, bl.x);
        split_pair(pbA.y, pbB.y, bh.y, bl.y);
        split_pair(pbA.z, pbB.z, bh.z, bl.z);
        split_pair(pbA.w, pbB.w, bh.w, bl.w);
        *reinterpret_cast<uint4*>(&BsH[bkp * NBST + bn4]) = bh;
        *reinterpret_cast<uint4*>(&BsL[bkp * NBST + bn4]) = bl;
    }
    __syncthreads();

    for (int k0 = 0; k0 < F_; k0 += 32) {
        const int s = (k0 >> 5) & 1;
        uint32_t* AsH = smx + s * XZ_STAGE;
        uint32_t* AsL = AsH + 128 * XAST;
        uint32_t* BsH = AsL + 128 * XAST;
        uint32_t* BsL = BsH + 16 * NBST;
        const bool more = (k0 + 32 < F_);

        if (more) {
            pa0 = *reinterpret_cast<const float4*>(
                &A[(size_t)(row0 + ar0) * F_ + k0 + 32 + ak4]);
            pa1 = *reinterpret_cast<const float4*>(
                &A[(size_t)(row0 + ar1) * F_ + k0 + 32 + ak4]);
            pbA = *reinterpret_cast<const float4*>(
                &Bm[(size_t)(k0 + 32 + 2 * bkp) * G_ + col0 + bn4]);
            pbB = *reinterpret_cast<const float4*>(
                &Bm[(size_t)(k0 + 32 + 2 * bkp + 1) * G_ + col0 + bn4]);
        }

#pragma unroll
        for (int st = 0; st < 2; st++) {       // two k16 steps (8 pairs each)
            const int kpb = st * 8;
            uint32_t aH[2][4], aL[2][4];
#pragma unroll
            for (int im = 0; im < 2; im++) {
                int p0 = (wm + im * 16 + gid) * XAST + kpb + tig;
                int p1 = p0 + 8 * XAST;
                aH[im][0] = AsH[p0];     aH[im][1] = AsH[p1];
                aH[im][2] = AsH[p0 + 4]; aH[im][3] = AsH[p1 + 4];
                aL[im][0] = AsL[p0];     aL[im][1] = AsL[p1];
                aL[im][2] = AsL[p0 + 4]; aL[im][3] = AsL[p1 + 4];
            }
#pragma unroll
            for (int in = 0; in < 4; in++) {
                int n = wn + in * 8 + gid;
                uint32_t bH[2], bL[2];
                bH[0] = BsH[(kpb + tig) * NBST + n];
                bH[1] = BsH[(kpb + tig + 4) * NBST + n];
                bL[0] = BsL[(kpb + tig) * NBST + n];
                bL[1] = BsL[(kpb + tig + 4) * NBST + n];
#pragma unroll
                for (int im = 0; im < 2; im++) {
                    mma_bf16(C[im][in], aH[im], bH);
                    mma_bf16(C[im][in], aL[im], bH);
                    mma_bf16(C[im][in], aH[im], bL);
                }
            }
        }

        if (more) {
            uint32_t* nAsH = smx + (s ^ 1) * XZ_STAGE;
            uint32_t* nAsL = nAsH + 128 * XAST;
            uint32_t* nBsH = nAsL + 128 * XAST;
            uint32_t* nBsL = nBsH + 16 * NBST;
            uint32_t h0, l0, h1, l1;
            split_pair(pa0.x, pa0.y, h0, l0); split_pair(pa0.z, pa0.w, h1, l1);
            *reinterpret_cast<uint2*>(&nAsH[ar0 * XAST + (ak4 >> 1)]) = make_uint2(h0, h1);
            *reinterpret_cast<uint2*>(&nAsL[ar0 * XAST + (ak4 >> 1)]) = make_uint2(l0, l1);
            split_pair(pa1.x, pa1.y, h0, l0); split_pair(pa1.z, pa1.w, h1, l1);
            *reinterpret_cast<uint2*>(&nAsH[ar1 * XAST + (ak4 >> 1)]) = make_uint2(h0, h1);
            *reinterpret_cast<uint2*>(&nAsL[ar1 * XAST + (ak4 >> 1)]) = make_uint2(l0, l1);
            uint4 bh, bl;
            split_pair(pbA.x, pbB.x, bh.x, bl.x);
            split_pair(pbA.y, pbB.y, bh.y, bl.y);
            split_pair(pbA.z, pbB.z, bh.z, bl.z);
            split_pair(pbA.w, pbB.w, bh.w, bl.w);
            *reinterpret_cast<uint4*>(&nBsH[bkp * NBST + bn4]) = bh;
            *reinterpret_cast<uint4*>(&nBsL[bkp * NBST + bn4]) = bl;
            __syncthreads();
        }
    }

    // transposed epilogue: g_xz[t][n][b]
#pragma unroll
    for (int im = 0; im < 2; im++) {
        int b = wm + im * 16 + gid;
#pragma unroll
        for (int in = 0; in < 4; in++) {
            int n = col0 + wn + in * 8 + 2 * tig;
            float bz0 = bias[n], bz1 = bias[n + 1];
            size_t p = ((size_t)t * G_ + n) * B_;
            g_xz[p + b]           = C[im][in][0] + bz0;
            g_xz[p + B_ + b]      = C[im][in][1] + bz1;
            g_xz[p + b + 8]       = C[im][in][2] + bz0;
            g_xz[p + B_ + b + 8]  = C[im][in][3] + bz1;
        }
    }
}

// ---------------------------------------------------------------------------
// Persistent LSTM, bf16 2-split tensor cores, z^T formulation (as R8).
// ---------------------------------------------------------------------------
#define WST   260
#define HST2  40
#define STSH  36
#define HCH   (64 * HST2)

__global__ __launch_bounds__(256)
void lstm_tc_kernel(const float* __restrict__ W_rec)
{
    extern __shared__ uint32_t sm[];
    uint32_t* WsH = sm;
    uint32_t* WsL = WsH + 64 * WST;
    uint32_t* Hsb = WsL + 64 * WST;
    float* stash  = reinterpret_cast<float*>(Hsb + 2 * 2 * HCH);
    float* cs     = stash + 64 * STSH;

    const int tid  = threadIdx.x;
    const int lane = tid & 31, wrp = tid >> 5;
    const int gid  = lane >> 2, tig = lane & 3;
    const int wm   = (wrp & 3) * 16;
    const int wnb  = (wrp >> 2) * 16;
    const int ub   = blockIdx.x >> 2;
    const int bb   = blockIdx.x & 3;
    const int bg0  = bb * 32;

    for (int idx = tid; idx < 64 * 256; idx += 256) {
        int kp = idx & 255, c = idx >> 8;
        int gc = (c >> 4) * U_ + ub * 16 + (c & 15);
        float w0 = W_rec[(size_t)(2 * kp) * G_ + gc];
        float w1 = W_rec[(size_t)(2 * kp + 1) * G_ + gc];
        split_pair(w0, w1, WsH[c * WST + kp], WsL[c * WST + kp]);
    }
    for (int i = tid; i < 16 * 32; i += 256) cs[i] = 0.f;
    __syncthreads();

    const int sr0 = tid >> 3, sb4 = (tid & 7) << 2;
    const int eb = tid & 31, eu2 = tid >> 5;

    for (int t = 0; t < T_; t++) {
        const uint32_t* hpH = (t == 0) ? g_h0p : (g_hpH + (size_t)(t - 1) * UP * B_);
        const uint32_t* hpL = (t == 0) ? g_h0p : (g_hpL + (size_t)(t - 1) * UP * B_);
        const float* xz_t = g_xz + (size_t)t * G_ * B_;

        float xzv[4][2];
#pragma unroll
        for (int g = 0; g < 4; g++)
#pragma unroll
            for (int j = 0; j < 2; j++)
                xzv[g][j] = xz_t[(size_t)(g * U_ + ub * 16 + 2 * eu2 + j) * B_ + bg0 + eb];

        float C[2][4];
#pragma unroll
        for (int in = 0; in < 2; in++)
#pragma unroll
            for (int r = 0; r < 4; r++) C[in][r] = 0.f;

        uint4 pfh0, pfh1, pfl0, pfl1;
        pfh0 = *reinterpret_cast<const uint4*>(&hpH[(size_t)sr0 * B_ + bg0 + sb4]);
        pfh1 = *reinterpret_cast<const uint4*>(&hpH[(size_t)(sr0 + 32) * B_ + bg0 + sb4]);
        pfl0 = *reinterpret_cast<const uint4*>(&hpL[(size_t)sr0 * B_ + bg0 + sb4]);
        pfl1 = *reinterpret_cast<const uint4*>(&hpL[(size_t)(sr0 + 32) * B_ + bg0 + sb4]);
        {
            uint32_t* bH = Hsb;
            uint32_t* bL = Hsb + HCH;
            *reinterpret_cast<uint4*>(&bH[sr0 * HST2 + sb4]) = pfh0;
            *reinterpret_cast<uint4*>(&bH[(sr0 + 32) * HST2 + sb4]) = pfh1;
            *reinterpret_cast<uint4*>(&bL[sr0 * HST2 + sb4]) = pfl0;
            *reinterpret_cast<uint4*>(&bL[(sr0 + 32) * HST2 + sb4]) = pfl1;
        }
        __syncthreads();

        for (int kc = 0; kc < 4; kc++) {
            uint32_t* bH = Hsb + (kc & 1) * 2 * HCH;
            uint32_t* bL = bH + HCH;
            const bool more = (kc < 3);

            if (more) {
                const uint32_t* nH = hpH + (size_t)(kc + 1) * 64 * B_;
                const uint32_t* nL = hpL + (size_t)(kc + 1) * 64 * B_;
                pfh0 = *reinterpret_cast<const uint4*>(&nH[(size_t)sr0 * B_ + bg0 + sb4]);
                pfh1 = *reinterpret_cast<const uint4*>(&nH[(size_t)(sr0 + 32) * B_ + bg0 + sb4]);
                pfl0 = *reinterpret_cast<const uint4*>(&nL[(size_t)sr0 * B_ + bg0 + sb4]);
                pfl1 = *reinterpret_cast<const uint4*>(&nL[(size_t)(sr0 + 32) * B_ + bg0 + sb4]);
            }

#pragma unroll
            for (int ks = 0; ks < 8; ks++) {
                const int kb = ks * 8;
                uint32_t aH[4], aL[4];
                {
                    int p0 = (wm + gid) * WST + kc * 64 + kb + tig;
                    int p1 = (wm + gid + 8) * WST + kc * 64 + kb + tig;
                    aH[0] = WsH[p0];     aH[1] = WsH[p1];
                    aH[2] = WsH[p0 + 4]; aH[3] = WsH[p1 + 4];
                    aL[0] = WsL[p0];     aL[1] = WsL[p1];
                    aL[2] = WsL[p0 + 4]; aL[3] = WsL[p1 + 4];
                }
#pragma unroll
                for (int in = 0; in < 2; in++) {
                    int n = wnb + in * 8 + gid;
                    uint32_t bHf[2], bLf[2];
                    bHf[0] = bH[(kb + tig) * HST2 + n];
                    bHf[1] = bH[(kb + tig + 4) * HST2 + n];
                    bLf[0] = bL[(kb + tig) * HST2 + n];
                    bLf[1] = bL[(kb + tig + 4) * HST2 + n];
                    mma_bf16(C[in], aH, bHf);
                    mma_bf16(C[in], aL, bHf);
                    mma_bf16(C[in], aH, bLf);
                }
            }

            if (more) {
                uint32_t* nbH = Hsb + ((kc + 1) & 1) * 2 * HCH;
                uint32_t* nbL = nbH + HCH;
                *reinterpret_cast<uint4*>(&nbH[sr0 * HST2 + sb4]) = pfh0;
                *reinterpret_cast<uint4*>(&nbH[(sr0 + 32) * HST2 + sb4]) = pfh1;
                *reinterpret_cast<uint4*>(&nbL[sr0 * HST2 + sb4]) = pfl0;
                *reinterpret_cast<uint4*>(&nbL[(sr0 + 32) * HST2 + sb4]) = pfl1;
                __syncthreads();
            }
        }

#pragma unroll
        for (int in = 0; in < 2; in++) {
            int n0 = wnb + in * 8 + 2 * tig;
            float2 v0 = { C[in][0], C[in][1] };
            float2 v1 = { C[in][2], C[in][3] };
            *reinterpret_cast<float2*>(&stash[(wm + gid) * STSH + n0])     = v0;
            *reinterpret_cast<float2*>(&stash[(wm + gid + 8) * STSH + n0]) = v1;
        }
        __syncthreads();

        float hv[2];
#pragma unroll
        for (int j = 0; j < 2; j++) {
            int ul = 2 * eu2 + j;
            float zi = stash[(0 * 16 + ul) * STSH + eb] + xzv[0][j];
            float zf = stash[(1 * 16 + ul) * STSH + eb] + xzv[1][j];
            float zg = stash[(2 * 16 + ul) * STSH + eb] + xzv[2][j];
            float zo = stash[(3 * 16 + ul) * STSH + eb] + xzv[3][j];
            float ig = 1.f / (1.f + __expf(-zi));
            float fg = 1.f / (1.f + __expf(-zf));
            float gg = 1.f - 2.f / (1.f + __expf(2.f * zg));
            float og = 1.f / (1.f + __expf(-zo));
            float cn = fg * cs[ul * 32 + eb] + ig * gg;
            cs[ul * 32 + eb] = cn;
            hv[j] = og * (1.f - 2.f / (1.f + __expf(2.f * cn)));
        }

        uint32_t hiP, loP;
        split_pair(hv[0], hv[1], hiP, loP);
        size_t pq = (size_t)t * UP * B_ + (size_t)(ub * 8 + eu2) * B_ + bg0 + eb;
        g_hpH[pq] = hiP;
        g_hpL[pq] = loP;

        __threadfence();
        __syncthreads();
        if (tid == 0) {
            atomicAdd(&g_bar, 1u);
            unsigned tgt = (unsigned)(NBLK * (t + 1));
            while (*((volatile unsigned*)&g_bar) < tgt) { }
            __threadfence();
        }
        __syncthreads();
    }
}

// ---------------------------------------------------------------------------
// GEMM 3 (bf16 2-split TC, double-buffered): out = relu(mask*(h@W_dense)+b)
// A read directly from g_hpH/g_hpL pairs ([k'][m] layout), staged [k'][m].
// B (W_dense) re-packed at staging into [k'][n].
// ---------------------------------------------------------------------------
__global__ __launch_bounds__(512)
void gemm_dense_tc(const float* __restrict__ Bm,
                   const float* __restrict__ bias,
                   const float* __restrict__ mask,
                   float* __restrict__ Cout)
{
    extern __shared__ uint32_t smx[];

    const int tid  = threadIdx.x;
    const int lane = tid & 31, w = tid >> 5;
    const int gid  = lane >> 2, tig = lane & 3;
    const int wm   = (w >> 2) * 32, wn = (w & 3) * 32;
    const int t    = blockIdx.y;
    const int col0 = blockIdx.x * 128;
    const uint32_t* AhH = g_hpH + (size_t)t * UP * B_;
    const uint32_t* AhL = g_hpL + (size_t)t * UP * B_;

    const int kp0 = tid >> 5, x4 = (tid & 31) << 2;   // one task each

    float C[2][4][4];
#pragma unroll
    for (int im = 0; im < 2; im++)
#pragma unroll
        for (int in = 0; in < 4; in++)
#pragma unroll
            for (int r = 0; r < 4; r++) C[im][in][r] = 0.f;

    uint4 pah, pal;
    float4 pbA, pbB;
    pah = *reinterpret_cast<const uint4*>(&AhH[(size_t)kp0 * B_ + x4]);
    pal = *reinterpret_cast<const uint4*>(&AhL[(size_t)kp0 * B_ + x4]);
    pbA = *reinterpret_cast<const float4*>(&Bm[(size_t)(2 * kp0) * CODES_ + col0 + x4]);
    pbB = *reinterpret_cast<const float4*>(&Bm[(size_t)(2 * kp0 + 1) * CODES_ + col0 + x4]);
    {
        uint32_t* AsH = smx;
        uint32_t* AsL = AsH + 16 * NBST;
        uint32_t* BsH = AsL + 16 * NBST;
        uint32_t* BsL = BsH + 16 * NBST;
        *reinterpret_cast<uint4*>(&AsH[kp0 * NBST + x4]) = pah;
        *reinterpret_cast<uint4*>(&AsL[kp0 * NBST + x4]) = pal;
        uint4 bh, bl;
        split_pair(pbA.x, pbB.x, bh.x, bl.x);
        split_pair(pbA.y, pbB.y, bh.y, bl.y);
        split_pair(pbA.z, pbB.z, bh.z, bl.z);
        split_pair(pbA.w, pbB.w, bh.w, bl.w);
        *reinterpret_cast<uint4*>(&BsH[kp0 * NBST + x4]) = bh;
        *reinterpret_cast<uint4*>(&BsL[kp0 * NBST + x4]) = bl;
    }
    __syncthreads();

    for (int k0 = 0; k0 < UP; k0 += 16) {    // 16 pairs = 32 K per block
        const int s = (k0 >> 4) & 1;
        uint32_t* AsH = smx + s * DN_STAGE;
        uint32_t* AsL = AsH + 16 * NBST;
        uint32_t* BsH = AsL + 16 * NBST;
        uint32_t* BsL = BsH + 16 * NBST;
        const bool more = (k0 + 16 < UP);

        if (more) {
            pah = *reinterpret_cast<const uint4*>(&AhH[(size_t)(k0 + 16 + kp0) * B_ + x4]);
            pal = *reinterpret_cast<const uint4*>(&AhL[(size_t)(k0 + 16 + kp0) * B_ + x4]);
            pbA = *reinterpret_cast<const float4*>(
                &Bm[(size_t)(2 * (k0 + 16 + kp0)) * CODES_ + col0 + x4]);
            pbB = *reinterpret_cast<const float4*>(
                &Bm[(size_t)(2 * (k0 + 16 + kp0) + 1) * CODES_ + col0 + x4]);
        }

#pragma unroll
        for (int st = 0; st < 2; st++) {
            const int kpb = st * 8;
            uint32_t aH[2][4], aL[2][4];
#pragma unroll
            for (int im = 0; im < 2; im++) {
                int m = wm + im * 16 + gid;
                int p0 = (kpb + tig) * NBST + m;
                aH[im][0] = aH[im][1] = 0;   // init to silence warnings
                aH[im][0] = AsH[p0];          aH[im][1] = AsH[p0 + 8];
                aH[im][2] = AsH[p0 + 4 * NBST];
                aH[im][3] = AsH[p0 + 4 * NBST + 8];
                aL[im][0] = AsL[p0];          aL[im][1] = AsL[p0 + 8];
                aL[im][2] = AsL[p0 + 4 * NBST];
                aL[im][3] = AsL[p0 + 4 * NBST + 8];
            }
#pragma unroll
            for (int in = 0; in < 4; in++) {
                int n = wn + in * 8 + gid;
                uint32_t bH[2], bL[2];
                bH[0] = BsH[(kpb + tig) * NBST + n];
                bH[1] = BsH[(kpb + tig + 4) * NBST + n];
                bL[0] = BsL[(kpb + tig) * NBST + n];
                bL[1] = BsL[(kpb + tig + 4) * NBST + n];
#pragma unroll
                for (int im = 0; im < 2; im++) {
                    mma_bf16(C[im][in], aH[im], bH);
                    mma_bf16(C[im][in], aL[im], bH);
                    mma_bf16(C[im][in], aH[im], bL);
                }
            }
        }

        if (more) {
            uint32_t* nAsH = smx + (s ^ 1) * DN_STAGE;
            uint32_t* nAsL = nAsH + 16 * NBST;
            uint32_t* nBsH = nAsL + 16 * NBST;
            uint32_t* nBsL = nBsH + 16 * NBST;
            *reinterpret_cast<uint4*>(&nAsH[kp0 * NBST + x4]) = pah;
            *reinterpret_cast<uint4*>(&nAsL[kp0 * NBST + x4]) = pal;
            uint4 bh, bl;
            split_pair(pbA.x, pbB.x, bh.x, bl.x);
            split_pair(pbA.y, pbB.y, bh.y, bl.y);
            split_pair(pbA.z, pbB.z, bh.z, bl.z);
            split_pair(pbA.w, pbB.w, bh.w, bl.w);
            *reinterpret_cast<uint4*>(&nBsH[kp0 * NBST + x4]) = bh;
            *reinterpret_cast<uint4*>(&nBsL[kp0 * NBST + x4]) = bl;
            __syncthreads();
        }
    }

#pragma unroll
    for (int im = 0; im < 2; im++) {
        int b = wm + im * 16 + gid;
        int r0 = t * 128 + b, r1 = r0 + 8;
        float m0 = mask[r0], m1 = mask[r1];
#pragma unroll
        for (int in = 0; in < 4; in++) {
            int n = col0 + wn + in * 8 + 2 * tig;
            float bz0 = bias[n], bz1 = bias[n + 1];
            Cout[(size_t)r0 * CODES_ + n]     = fmaxf(C[im][in][0] * m0 + bz0, 0.f);
            Cout[(size_t)r0 * CODES_ + n + 1] = fmaxf(C[im][in][1] * m0 + bz1, 0.f);
            Cout[(size_t)r1 * CODES_ + n]     = fmaxf(C[im][in][2] * m1 + bz0, 0.f);
            Cout[(size_t)r1 * CODES_ + n + 1] = fmaxf(C[im][in][3] * m1 + bz1, 0.f);
        }
    }
}

// ---------------------------------------------------------------------------
__global__ __launch_bounds__(256)
void softmax_kernel(float* __restrict__ out)
{
    __shared__ float red[256];
    const int row = blockIdx.x;
    const int tid = threadIdx.x;
    float* p = out + (size_t)row * CODES_;

    float v[4];
    float m = -1e30f;
#pragma unroll
    for (int i = 0; i < 4; i++) {
        v[i] = p[tid + i * 256];
        m = fmaxf(m, v[i]);
    }
    red[tid] = m;
    __syncthreads();
    for (int s = 128; s > 0; s >>= 1) {
        if (tid < s) red[tid] = fmaxf(red[tid], red[tid + s]);
        __syncthreads();
    }
    m = red[0];
    __syncthreads();

    float sum = 0.f;
#pragma unroll
    for (int i = 0; i < 4; i++) {
        v[i] = __expf(v[i] - m);
        sum += v[i];
    }
    red[tid] = sum;
    __syncthreads();
    for (int s = 128; s > 0; s >>= 1) {
        if (tid < s) red[tid] += red[tid + s];
        __syncthreads();
    }
    float inv = 1.f / red[0];
#pragma unroll
    for (int i = 0; i < 4; i++) p[tid + i * 256] = v[i] * inv;
}

// ---------------------------------------------------------------------------
extern "C" void kernel_launch(void* const* d_in, const int* in_sizes, int n_in,
                              void* d_out, int out_size)
{
    const float* x       = (const float*)d_in[0];
    const float* mask    = (const float*)d_in[1];
    const float* W_in    = (const float*)d_in[2];
    const float* W_rec   = (const float*)d_in[3];
    const float* b_lstm  = (const float*)d_in[4];
    const float* W_dense = (const float*)d_in[5];
    const float* b_dense = (const float*)d_in[6];
    float* out = (float*)d_out;

    const int smem_xz    = 2 * XZ_STAGE * 4;
    const int smem_dense = 2 * DN_STAGE * 4;
    const int smem_lstm  = (2 * 64 * WST + 2 * 2 * HCH + 64 * STSH + 16 * 32) * 4;
    static int attr_set = 0;
    if (!attr_set) {
        cudaFuncSetAttribute(gemm_xz_tc,
                             cudaFuncAttributeMaxDynamicSharedMemorySize, smem_xz);
        cudaFuncSetAttribute(gemm_dense_tc,
                             cudaFuncAttributeMaxDynamicSharedMemorySize, smem_dense);
        cudaFuncSetAttribute(lstm_tc_kernel,
                             cudaFuncAttributeMaxDynamicSharedMemorySize, smem_lstm);
        attr_set = 1;
    }

    init_kernel<<<(UP * B_ + 255) / 256, 256>>>();

    {   // xz = x @ W_in + b  (bf16 2-split TC, transposed output)
        dim3 grid(G_ / 128, T_);
        gemm_xz_tc<<<grid, 512, smem_xz>>>(x, W_in, b_lstm);
    }

    lstm_tc_kernel<<<NBLK, 256, smem_lstm>>>(W_rec);

    {   // dense + mask + relu (bf16 2-split TC, A from h pairs)
        dim3 grid(CODES_ / 128, T_);
        gemm_dense_tc<<<grid, 512, smem_dense>>>(W_dense, b_dense, mask, out);
    }

    softmax_kernel<<<T_ * B_, 256>>>(out);
}